// round 4
// baseline (speedup 1.0000x reference)
#include <cuda_runtime.h>
#include <cuda_bf16.h>
#include <math.h>

#define EPSV 1e-5f

constexpr int B_  = 8;
constexpr int N_  = 16384;
constexpr int C_  = 256;
constexpr int K_  = 16;
constexpr int M_  = B_ * N_;       // 131072 points
constexpr int C2_ = 2 * C_;        // 512
constexpr int O_  = K_ * 3;        // 48 offset outputs
constexpr int NCHUNK_ = 128;       // pooling chunks per batch (N_/128)

// ---------------- scratch (device globals; no allocs allowed) ----------------
__device__ float g_x1[(size_t)M_ * C_];
__device__ float g_x2[(size_t)M_ * C_];
__device__ float g_x3[(size_t)M_ * C2_];
__device__ float g_voted[(size_t)M_ * O_];
__device__ float g_ebuf[(size_t)M_ * K_];
__device__ float g_partial[(size_t)B_ * NCHUNK_ * K_ * C_];
__device__ float g_kpsum[B_ * O_];      // vote sums -> kp_pos
__device__ float g_s[B_ * K_];          // softmax denominators
__device__ float g_kpfeat[B_ * K_ * C_];
__device__ float g_sc1[C_],  g_sh1[C_];
__device__ float g_sc2[C_],  g_sh2[C_];
__device__ float g_sc3[C2_], g_sh3[C2_];
__device__ float g_scm1[C_], g_shm1[C_];
__device__ float g_scm2[C_], g_shm2[C_];

// ---------------- BN fold + zero accumulators ----------------
__global__ void prep_kernel(
    const float* __restrict__ g1, const float* __restrict__ b1,
    const float* __restrict__ m1, const float* __restrict__ v1,
    const float* __restrict__ g2, const float* __restrict__ b2,
    const float* __restrict__ m2, const float* __restrict__ v2,
    const float* __restrict__ g3, const float* __restrict__ b3,
    const float* __restrict__ m3, const float* __restrict__ v3,
    const float* __restrict__ gm1, const float* __restrict__ bm1,
    const float* __restrict__ mm1, const float* __restrict__ vm1,
    const float* __restrict__ gm2, const float* __restrict__ bm2,
    const float* __restrict__ mm2, const float* __restrict__ vm2)
{
    int i = threadIdx.x;  // 512 threads
    if (i < C_) {
        float s;
        s = g1[i] * rsqrtf(v1[i] + EPSV);  g_sc1[i] = s;  g_sh1[i] = b1[i] - m1[i] * s;
        s = g2[i] * rsqrtf(v2[i] + EPSV);  g_sc2[i] = s;  g_sh2[i] = b2[i] - m2[i] * s;
        s = gm1[i] * rsqrtf(vm1[i] + EPSV); g_scm1[i] = s; g_shm1[i] = bm1[i] - mm1[i] * s;
        s = gm2[i] * rsqrtf(vm2[i] + EPSV); g_scm2[i] = s; g_shm2[i] = bm2[i] - mm2[i] * s;
    }
    if (i < C2_) {
        float s = g3[i] * rsqrtf(v3[i] + EPSV);
        g_sc3[i] = s;  g_sh3[i] = b3[i] - m3[i] * s;
    }
    if (i < B_ * O_) g_kpsum[i] = 0.0f;
    if (i < B_ * K_) g_s[i] = 0.0f;
}

// ---------------- 128x128x16 register-blocked SGEMM, fused BN+ReLU ----------------
// Cout[m,n] = relu( dot(A[m,:], W[n,:]) * scale[n] + shift[n] )
// A: MxKd row-major, W: Nd x Kd row-major (NT gemm, K contiguous both sides).
// Double-buffered SMEM + register prefetch: one __syncthreads per 16-k tile,
// 1024 FMAs/thread between barriers; global loads overlap the live tile.
__global__ __launch_bounds__(256, 2)
void sgemm_bn_relu(const float* __restrict__ A, const float* __restrict__ W,
                   float* __restrict__ Cout,
                   const float* __restrict__ scale, const float* __restrict__ shift,
                   int Kd, int Nd)
{
    __shared__ float As[2][16][128];
    __shared__ float Ws[2][16][128];

    const int tid = threadIdx.x;
    const int m0 = blockIdx.y * 128;
    const int n0 = blockIdx.x * 128;

    const int lrow = tid >> 1;           // 0..127
    const int lcol = (tid & 1) * 4;      // 0 or 4 (k offset of first float4)
    const float* Ap = A + (size_t)(m0 + lrow) * Kd + lcol;
    const float* Wp = W + (size_t)(n0 + lrow) * Kd + lcol;

    const int ty = tid >> 4;             // 0..15  (m micro-tile)
    const int tx = tid & 15;             // 0..15  (n micro-tile)

    float acc[8][8];
#pragma unroll
    for (int i = 0; i < 8; i++)
#pragma unroll
        for (int j = 0; j < 8; j++) acc[i][j] = 0.0f;

    // prologue: fetch tile 0 (k 0..15) and stage it into buffer 0
    float4 av0 = *(const float4*)(Ap);
    float4 av1 = *(const float4*)(Ap + 8);
    float4 wv0 = *(const float4*)(Wp);
    float4 wv1 = *(const float4*)(Wp + 8);
    As[0][lcol + 0][lrow] = av0.x; As[0][lcol + 1][lrow] = av0.y;
    As[0][lcol + 2][lrow] = av0.z; As[0][lcol + 3][lrow] = av0.w;
    As[0][lcol + 8][lrow] = av1.x; As[0][lcol + 9][lrow] = av1.y;
    As[0][lcol +10][lrow] = av1.z; As[0][lcol +11][lrow] = av1.w;
    Ws[0][lcol + 0][lrow] = wv0.x; Ws[0][lcol + 1][lrow] = wv0.y;
    Ws[0][lcol + 2][lrow] = wv0.z; Ws[0][lcol + 3][lrow] = wv0.w;
    Ws[0][lcol + 8][lrow] = wv1.x; Ws[0][lcol + 9][lrow] = wv1.y;
    Ws[0][lcol +10][lrow] = wv1.z; Ws[0][lcol +11][lrow] = wv1.w;
    __syncthreads();

    int buf = 0;
    for (int k0 = 0; k0 < Kd; k0 += 16) {
        const bool has_next = (k0 + 16 < Kd);
        // issue next tile's global loads before touching this tile's smem
        if (has_next) {
            av0 = *(const float4*)(Ap + k0 + 16);
            av1 = *(const float4*)(Ap + k0 + 24);
            wv0 = *(const float4*)(Wp + k0 + 16);
            wv1 = *(const float4*)(Wp + k0 + 24);
        }

#pragma unroll
        for (int k = 0; k < 16; k++) {
            float a[8], b[8];
            *(float4*)(a)     = *(const float4*)&As[buf][k][ty * 8];
            *(float4*)(a + 4) = *(const float4*)&As[buf][k][ty * 8 + 4];
            *(float4*)(b)     = *(const float4*)&Ws[buf][k][tx * 8];
            *(float4*)(b + 4) = *(const float4*)&Ws[buf][k][tx * 8 + 4];
#pragma unroll
            for (int i = 0; i < 8; i++)
#pragma unroll
                for (int j = 0; j < 8; j++)
                    acc[i][j] = fmaf(a[i], b[j], acc[i][j]);
        }

        if (has_next) {
            const int nb = buf ^ 1;
            As[nb][lcol + 0][lrow] = av0.x; As[nb][lcol + 1][lrow] = av0.y;
            As[nb][lcol + 2][lrow] = av0.z; As[nb][lcol + 3][lrow] = av0.w;
            As[nb][lcol + 8][lrow] = av1.x; As[nb][lcol + 9][lrow] = av1.y;
            As[nb][lcol +10][lrow] = av1.z; As[nb][lcol +11][lrow] = av1.w;
            Ws[nb][lcol + 0][lrow] = wv0.x; Ws[nb][lcol + 1][lrow] = wv0.y;
            Ws[nb][lcol + 2][lrow] = wv0.z; Ws[nb][lcol + 3][lrow] = wv0.w;
            Ws[nb][lcol + 8][lrow] = wv1.x; Ws[nb][lcol + 9][lrow] = wv1.y;
            Ws[nb][lcol +10][lrow] = wv1.z; Ws[nb][lcol +11][lrow] = wv1.w;
            buf = nb;
            __syncthreads();
        }
    }

    float sc[8], sh[8];
#pragma unroll
    for (int j = 0; j < 8; j++) {
        sc[j] = scale[n0 + tx * 8 + j];
        sh[j] = shift[n0 + tx * 8 + j];
    }
#pragma unroll
    for (int i = 0; i < 8; i++) {
        const int m = m0 + ty * 8 + i;
        float o[8];
#pragma unroll
        for (int j = 0; j < 8; j++)
            o[j] = fmaxf(fmaf(acc[i][j], sc[j], sh[j]), 0.0f);
        float* cp = Cout + (size_t)m * Nd + n0 + tx * 8;
        *(float4*)(cp)     = *(float4*)(o);
        *(float4*)(cp + 4) = *(float4*)(o + 4);
    }
}

// ---------------- offsets GEMM (M x 48, K=512) fused with vote + mean partials ----------------
// one block = 64 points; 256 threads; micro-tile 4 points x 3 outputs
__global__ __launch_bounds__(256)
void offsets_kernel(const float* __restrict__ Wo, const float* __restrict__ bo,
                    const float* __restrict__ xyz)
{
    __shared__ float As[16][64];
    __shared__ float Ws[16][48];
    __shared__ float red[16][48];

    const int tid = threadIdx.x;
    const int m0 = blockIdx.x * 64;
    const int arow = tid >> 2;           // 0..63
    const int akb  = (tid & 3) * 4;      // 0,4,8,12
    const int ty = tid >> 4;             // 0..15 -> points ty*4..ty*4+3
    const int tx = tid & 15;             // 0..15 -> outputs tx*3..tx*3+2

    float acc[4][3];
#pragma unroll
    for (int i = 0; i < 4; i++)
#pragma unroll
        for (int j = 0; j < 3; j++) acc[i][j] = 0.0f;

    // prologue fetch
    float4 av = *(const float4*)(g_x3 + (size_t)(m0 + arow) * C2_ + akb);
    float wv[3];
#pragma unroll
    for (int t = 0; t < 3; t++) {
        int idx = tid * 3 + t;           // 0..767
        int n = idx >> 4, kk = idx & 15;
        wv[t] = Wo[(size_t)n * C2_ + kk];
    }

    for (int k0 = 0; k0 < C2_; k0 += 16) {
        __syncthreads();
        As[akb + 0][arow] = av.x; As[akb + 1][arow] = av.y;
        As[akb + 2][arow] = av.z; As[akb + 3][arow] = av.w;
#pragma unroll
        for (int t = 0; t < 3; t++) {
            int idx = tid * 3 + t;
            Ws[idx & 15][idx >> 4] = wv[t];
        }
        __syncthreads();

        if (k0 + 16 < C2_) {
            av = *(const float4*)(g_x3 + (size_t)(m0 + arow) * C2_ + k0 + 16 + akb);
#pragma unroll
            for (int t = 0; t < 3; t++) {
                int idx = tid * 3 + t;
                int n = idx >> 4, kk = idx & 15;
                wv[t] = Wo[(size_t)n * C2_ + k0 + 16 + kk];
            }
        }

#pragma unroll
        for (int k = 0; k < 16; k++) {
            float a[4], b[3];
#pragma unroll
            for (int i = 0; i < 4; i++) a[i] = As[k][ty * 4 + i];
#pragma unroll
            for (int j = 0; j < 3; j++) b[j] = Ws[k][tx * 3 + j];
#pragma unroll
            for (int i = 0; i < 4; i++)
#pragma unroll
                for (int j = 0; j < 3; j++)
                    acc[i][j] = fmaf(a[i], b[j], acc[i][j]);
        }
    }

    const int b = m0 / N_;
    float psum[3] = {0.f, 0.f, 0.f};
#pragma unroll
    for (int i = 0; i < 4; i++) {
        const int m = m0 + ty * 4 + i;
#pragma unroll
        for (int j = 0; j < 3; j++) {
            const int o = tx * 3 + j;
            float v = acc[i][j] + bo[o] + xyz[(size_t)m * 3 + (o % 3)];
            g_voted[(size_t)m * O_ + o] = v;
            psum[j] += v;
        }
    }
#pragma unroll
    for (int j = 0; j < 3; j++) red[ty][tx * 3 + j] = psum[j];
    __syncthreads();
    if (tid < O_) {
        float s = 0.0f;
#pragma unroll
        for (int r = 0; r < 16; r++) s += red[r][tid];
        atomicAdd(&g_kpsum[b * O_ + tid], s);
    }
}

// ---------------- kp_pos = vote mean; also emit to output ----------------
__global__ void finalize_kp(float* __restrict__ out)
{
    int i = blockIdx.x * blockDim.x + threadIdx.x;
    if (i < B_ * O_) {
        float v = g_kpsum[i] * (1.0f / (float)N_);
        g_kpsum[i] = v;     // reuse as kp_pos for dist kernel
        out[i] = v;         // kp_pos is the first output
    }
}

// ---------------- dist -> exp(-dist) and per-(b,k) denominator ----------------
__global__ __launch_bounds__(256)
void dist_kernel()
{
    __shared__ float kp[O_];
    __shared__ float wsum[8][K_];
    const int b = blockIdx.y;
    const int tid = threadIdx.x;
    const int n = blockIdx.x * 256 + tid;
    if (tid < O_) kp[tid] = g_kpsum[b * O_ + tid];
    __syncthreads();

    const size_t m = (size_t)b * N_ + n;
    float vt[O_];
    const float4* vp = (const float4*)&g_voted[m * O_];
#pragma unroll
    for (int q = 0; q < O_ / 4; q++) ((float4*)vt)[q] = vp[q];

    float e[K_];
#pragma unroll
    for (int k = 0; k < K_; k++) {
        float dx = vt[k * 3 + 0] - kp[k * 3 + 0];
        float dy = vt[k * 3 + 1] - kp[k * 3 + 1];
        float dz = vt[k * 3 + 2] - kp[k * 3 + 2];
        float d = sqrtf(dx * dx + dy * dy + dz * dz);
        e[k] = __expf(-d);
    }
    float4* ep = (float4*)&g_ebuf[m * K_];
#pragma unroll
    for (int q = 0; q < K_ / 4; q++) ep[q] = ((float4*)e)[q];

    // block-level sum per k
    const int lane = tid & 31, wid = tid >> 5;
#pragma unroll
    for (int k = 0; k < K_; k++) {
        float s = e[k];
#pragma unroll
        for (int off = 16; off > 0; off >>= 1)
            s += __shfl_xor_sync(0xffffffffu, s, off);
        if (lane == 0) wsum[wid][k] = s;
    }
    __syncthreads();
    if (tid < K_) {
        float s = 0.0f;
#pragma unroll
        for (int w = 0; w < 8; w++) s += wsum[w][tid];
        atomicAdd(&g_s[b * K_ + tid], s);
    }
}

// ---------------- pooling stage 1: per-chunk partial kp_feat ----------------
// block = (chunk of 128 points, b); thread c accumulates 16 keypoint features
__global__ __launch_bounds__(256)
void pool1_kernel(const float* __restrict__ fused)
{
    __shared__ float w_s[128][K_];
    __shared__ float sinv[K_];
    const int b = blockIdx.y, cid = blockIdx.x;
    const int tid = threadIdx.x;
    const int n0 = cid * 128;

    if (tid < K_) sinv[tid] = 1.0f / g_s[b * K_ + tid];
    __syncthreads();

    // load 128x16 exp values, normalize -> weights
#pragma unroll
    for (int t = 0; t < 2; t++) {
        int f4 = tid * 2 + t;            // 0..511
        int flat = f4 * 4;
        int n = flat >> 4, k0 = flat & 15;
        float4 v = *(const float4*)&g_ebuf[((size_t)b * N_ + n0 + n) * K_ + k0];
        w_s[n][k0 + 0] = v.x * sinv[k0 + 0];
        w_s[n][k0 + 1] = v.y * sinv[k0 + 1];
        w_s[n][k0 + 2] = v.z * sinv[k0 + 2];
        w_s[n][k0 + 3] = v.w * sinv[k0 + 3];
    }
    __syncthreads();

    float acc[K_];
#pragma unroll
    for (int k = 0; k < K_; k++) acc[k] = 0.0f;

    const float* fp = fused + ((size_t)b * N_ + n0) * C_ + tid;
#pragma unroll 4
    for (int n = 0; n < 128; n++) {
        float f = fp[(size_t)n * C_];
#pragma unroll
        for (int k = 0; k < K_; k++)
            acc[k] = fmaf(f, w_s[n][k], acc[k]);
    }
    float* pp = &g_partial[(((size_t)b * NCHUNK_ + cid) * K_) * C_ + tid];
#pragma unroll
    for (int k = 0; k < K_; k++) pp[(size_t)k * C_] = acc[k];
}

// ---------------- pooling stage 2: reduce chunks ----------------
__global__ void pool2_kernel()
{
    const int b = blockIdx.y, k = blockIdx.x, c = threadIdx.x;
    float s = 0.0f;
    const float* pp = &g_partial[(((size_t)b * NCHUNK_) * K_ + k) * C_ + c];
    for (int cid = 0; cid < NCHUNK_; cid++)
        s += pp[(size_t)cid * K_ * C_];
    g_kpfeat[(b * K_ + k) * C_ + c] = s;
}

// ---------------- keypoint MLP: 3 fused layers, one block per (b,k) row ----------------
__global__ __launch_bounds__(256)
void mlp_kernel(const float* __restrict__ Wm1, const float* __restrict__ Wm2,
                const float* __restrict__ Wm3, float* __restrict__ out)
{
    __shared__ float f0[C_];
    __shared__ float f1[C_];
    const int r = blockIdx.x;       // 0..127
    const int d = threadIdx.x;      // 0..255

    f0[d] = g_kpfeat[r * C_ + d];
    __syncthreads();

    // layer 1
    {
        const float* w = Wm1 + (size_t)d * C_;
        float acc = 0.0f;
#pragma unroll 8
        for (int c = 0; c < C_; c++) acc = fmaf(f0[c], w[c], acc);
        f1[d] = fmaxf(fmaf(acc, g_scm1[d], g_shm1[d]), 0.0f);
    }
    __syncthreads();
    // layer 2
    float v2;
    {
        const float* w = Wm2 + (size_t)d * C_;
        float acc = 0.0f;
#pragma unroll 8
        for (int c = 0; c < C_; c++) acc = fmaf(f1[c], w[c], acc);
        v2 = fmaxf(fmaf(acc, g_scm2[d], g_shm2[d]), 0.0f);
    }
    __syncthreads();
    f0[d] = v2;
    __syncthreads();
    // layer 3
    {
        const float* w = Wm3 + (size_t)d * C_;
        float acc = 0.0f;
#pragma unroll 8
        for (int c = 0; c < C_; c++) acc = fmaf(f0[c], w[c], acc);
        out[B_ * O_ + r * C_ + d] = acc;   // y follows kp_pos in the output
    }
}

extern "C" void kernel_launch(void* const* d_in, const int* in_sizes, int n_in,
                              void* d_out, int out_size)
{
    const float* fused = (const float*)d_in[0];
    const float* xyz   = (const float*)d_in[1];
    const float* W1 = (const float*)d_in[2];
    const float* g1 = (const float*)d_in[3];
    const float* b1 = (const float*)d_in[4];
    const float* m1 = (const float*)d_in[5];
    const float* v1 = (const float*)d_in[6];
    const float* W2 = (const float*)d_in[7];
    const float* g2 = (const float*)d_in[8];
    const float* b2 = (const float*)d_in[9];
    const float* m2 = (const float*)d_in[10];
    const float* v2 = (const float*)d_in[11];
    const float* W3 = (const float*)d_in[12];
    const float* g3 = (const float*)d_in[13];
    const float* b3 = (const float*)d_in[14];
    const float* m3 = (const float*)d_in[15];
    const float* v3 = (const float*)d_in[16];
    const float* Wo = (const float*)d_in[17];
    const float* bo = (const float*)d_in[18];
    const float* Wm1 = (const float*)d_in[19];
    const float* gm1 = (const float*)d_in[20];
    const float* bm1 = (const float*)d_in[21];
    const float* mm1 = (const float*)d_in[22];
    const float* vm1 = (const float*)d_in[23];
    const float* Wm2 = (const float*)d_in[24];
    const float* gm2 = (const float*)d_in[25];
    const float* bm2 = (const float*)d_in[26];
    const float* mm2 = (const float*)d_in[27];
    const float* vm2 = (const float*)d_in[28];
    const float* Wm3 = (const float*)d_in[29];
    float* out = (float*)d_out;

    prep_kernel<<<1, 512>>>(g1, b1, m1, v1, g2, b2, m2, v2, g3, b3, m3, v3,
                            gm1, bm1, mm1, vm1, gm2, bm2, mm2, vm2);

    // resolve scratch symbol addresses once (host side; not a stream op)
    static float *x1 = nullptr, *x2 = nullptr, *x3 = nullptr;
    static float *sc1, *sh1, *sc2, *sh2, *sc3, *sh3;
    if (!x1) {
        cudaGetSymbolAddress((void**)&x1, g_x1);
        cudaGetSymbolAddress((void**)&x2, g_x2);
        cudaGetSymbolAddress((void**)&x3, g_x3);
        cudaGetSymbolAddress((void**)&sc1, g_sc1);
        cudaGetSymbolAddress((void**)&sh1, g_sh1);
        cudaGetSymbolAddress((void**)&sc2, g_sc2);
        cudaGetSymbolAddress((void**)&sh2, g_sh2);
        cudaGetSymbolAddress((void**)&sc3, g_sc3);
        cudaGetSymbolAddress((void**)&sh3, g_sh3);
    }

    dim3 grd1(C_ / 128, M_ / 128);
    sgemm_bn_relu<<<grd1, 256>>>(fused, W1, x1, sc1, sh1, C_, C_);
    sgemm_bn_relu<<<grd1, 256>>>(x1, W2, x2, sc2, sh2, C_, C_);
    dim3 grd3(C2_ / 128, M_ / 128);
    sgemm_bn_relu<<<grd3, 256>>>(x2, W3, x3, sc3, sh3, C_, C2_);

    offsets_kernel<<<M_ / 64, 256>>>(Wo, bo, xyz);
    finalize_kp<<<(B_ * O_ + 255) / 256, 256>>>(out);

    dim3 gd(N_ / 256, B_);
    dist_kernel<<<gd, 256>>>();

    dim3 gp1(NCHUNK_, B_);
    pool1_kernel<<<gp1, 256>>>(fused);
    dim3 gp2(K_, B_);
    pool2_kernel<<<gp2, C_>>>();

    mlp_kernel<<<B_ * K_, C_>>>(Wm1, Wm2, Wm3, out);
}

// round 6
// speedup vs baseline: 1.5879x; 1.5879x over previous
#include <cuda_runtime.h>
#include <cuda_bf16.h>
#include <math.h>

#define EPSV 1e-5f

constexpr int B_  = 8;
constexpr int N_  = 16384;
constexpr int C_  = 256;
constexpr int K_  = 16;
constexpr int M_  = B_ * N_;       // 131072 points
constexpr int C2_ = 2 * C_;        // 512
constexpr int O_  = K_ * 3;        // 48 offset outputs
constexpr int NCHUNK_ = 128;       // pooling chunks per batch (N_/128)

// ---------------- scratch (device globals; no allocs allowed) ----------------
// activations as split-bf16 planes (hi, lo)
__device__ __nv_bfloat16 g_fh[(size_t)M_ * C_];
__device__ __nv_bfloat16 g_fl[(size_t)M_ * C_];
__device__ __nv_bfloat16 g_x1h[(size_t)M_ * C_];
__device__ __nv_bfloat16 g_x1l[(size_t)M_ * C_];
__device__ __nv_bfloat16 g_x2h[(size_t)M_ * C_];
__device__ __nv_bfloat16 g_x2l[(size_t)M_ * C_];
__device__ float g_x3[(size_t)M_ * C2_];
// weight split planes
__device__ __nv_bfloat16 g_w1h[C_ * C_],  g_w1l[C_ * C_];
__device__ __nv_bfloat16 g_w2h[C_ * C_],  g_w2l[C_ * C_];
__device__ __nv_bfloat16 g_w3h[C2_ * C_], g_w3l[C2_ * C_];
// downstream scratch (unchanged from passing kernel)
__device__ float g_voted[(size_t)M_ * O_];
__device__ float g_ebuf[(size_t)M_ * K_];
__device__ float g_partial[(size_t)B_ * NCHUNK_ * K_ * C_];
__device__ float g_kpsum[B_ * O_];
__device__ float g_s[B_ * K_];
__device__ float g_kpfeat[B_ * K_ * C_];
__device__ float g_sc1[C_],  g_sh1[C_];
__device__ float g_sc2[C_],  g_sh2[C_];
__device__ float g_sc3[C2_], g_sh3[C2_];
__device__ float g_scm1[C_], g_shm1[C_];
__device__ float g_scm2[C_], g_shm2[C_];

// ---------------- BN fold + zero accumulators ----------------
__global__ void prep_kernel(
    const float* __restrict__ g1, const float* __restrict__ b1,
    const float* __restrict__ m1, const float* __restrict__ v1,
    const float* __restrict__ g2, const float* __restrict__ b2,
    const float* __restrict__ m2, const float* __restrict__ v2,
    const float* __restrict__ g3, const float* __restrict__ b3,
    const float* __restrict__ m3, const float* __restrict__ v3,
    const float* __restrict__ gm1, const float* __restrict__ bm1,
    const float* __restrict__ mm1, const float* __restrict__ vm1,
    const float* __restrict__ gm2, const float* __restrict__ bm2,
    const float* __restrict__ mm2, const float* __restrict__ vm2)
{
    int i = threadIdx.x;  // 512 threads
    if (i < C_) {
        float s;
        s = g1[i] * rsqrtf(v1[i] + EPSV);  g_sc1[i] = s;  g_sh1[i] = b1[i] - m1[i] * s;
        s = g2[i] * rsqrtf(v2[i] + EPSV);  g_sc2[i] = s;  g_sh2[i] = b2[i] - m2[i] * s;
        s = gm1[i] * rsqrtf(vm1[i] + EPSV); g_scm1[i] = s; g_shm1[i] = bm1[i] - mm1[i] * s;
        s = gm2[i] * rsqrtf(vm2[i] + EPSV); g_scm2[i] = s; g_shm2[i] = bm2[i] - mm2[i] * s;
    }
    if (i < C2_) {
        float s = g3[i] * rsqrtf(v3[i] + EPSV);
        g_sc3[i] = s;  g_sh3[i] = b3[i] - m3[i] * s;
    }
    if (i < B_ * O_) g_kpsum[i] = 0.0f;
    if (i < B_ * K_) g_s[i] = 0.0f;
}

// ---------------- fp32 -> (hi, lo) bf16 split, float4-vectorized ----------------
__global__ void split_bf16_kernel(const float4* __restrict__ in,
                                  __nv_bfloat162* __restrict__ h,
                                  __nv_bfloat162* __restrict__ l, int n4)
{
    int i = blockIdx.x * blockDim.x + threadIdx.x;
    if (i >= n4) return;
    float4 v = in[i];
    __nv_bfloat16 h0 = __float2bfloat16(v.x);
    __nv_bfloat16 h1 = __float2bfloat16(v.y);
    __nv_bfloat16 h2 = __float2bfloat16(v.z);
    __nv_bfloat16 h3 = __float2bfloat16(v.w);
    __nv_bfloat16 l0 = __float2bfloat16(v.x - __bfloat162float(h0));
    __nv_bfloat16 l1 = __float2bfloat16(v.y - __bfloat162float(h1));
    __nv_bfloat16 l2 = __float2bfloat16(v.z - __bfloat162float(h2));
    __nv_bfloat16 l3 = __float2bfloat16(v.w - __bfloat162float(h3));
    h[2 * i]     = __nv_bfloat162(h0, h1);
    h[2 * i + 1] = __nv_bfloat162(h2, h3);
    l[2 * i]     = __nv_bfloat162(l0, l1);
    l[2 * i + 1] = __nv_bfloat162(l2, l3);
}

// ---------------- mma helpers ----------------
__device__ __forceinline__ void mma16816(float* d,
    unsigned a0, unsigned a1, unsigned a2, unsigned a3,
    unsigned b0, unsigned b1)
{
    asm volatile(
        "mma.sync.aligned.m16n8k16.row.col.f32.bf16.bf16.f32 "
        "{%0,%1,%2,%3}, {%4,%5,%6,%7}, {%8,%9}, {%0,%1,%2,%3};\n"
        : "+f"(d[0]), "+f"(d[1]), "+f"(d[2]), "+f"(d[3])
        : "r"(a0), "r"(a1), "r"(a2), "r"(a3), "r"(b0), "r"(b1));
}

__device__ __forceinline__ void cp16(void* smem, const void* gmem)
{
    unsigned s = (unsigned)__cvta_generic_to_shared(smem);
    asm volatile("cp.async.cg.shared.global [%0], [%1], 16;\n" :: "r"(s), "l"(gmem));
}
#define CP_COMMIT()  asm volatile("cp.async.commit_group;\n")
#define CP_WAIT(n)   asm volatile("cp.async.wait_group %0;\n" :: "n"(n))

// ---------------- split-bf16 tensor-core GEMM, fused BN+ReLU ----------------
// C[m,n] = relu( dot(A[m,:], W[n,:]) * scale[n] + shift[n] ),  A = Ah+Al, W = Wh+Wl
// three mma products: Ah*Wh + Ah*Wl + Al*Wh (Al*Wl ~ 2^-18, dropped)
// tiles: 128x128x16; 8 warps of 64x32; double-buffered smem via cp.async.
// BF16_OUT: write split-bf16 planes (for chained GEMM); else fp32.
constexpr int SROW = 24;  // 16 data bf16 + 8 pad -> 48B row stride (conflict-free, 16B aligned)

template<bool BF16_OUT>
__global__ __launch_bounds__(256, 2)
void gemm_mma_bn_relu(const __nv_bfloat16* __restrict__ Ah,
                      const __nv_bfloat16* __restrict__ Al,
                      const __nv_bfloat16* __restrict__ Wh,
                      const __nv_bfloat16* __restrict__ Wl,
                      float* __restrict__ outF,
                      __nv_bfloat16* __restrict__ outH,
                      __nv_bfloat16* __restrict__ outL,
                      const float* __restrict__ scale,
                      const float* __restrict__ shift,
                      int Kd, int Nd)
{
    // planes: 0=Ah 1=Al 2=Wh 3=Wl
    __shared__ __nv_bfloat16 sm[2][4][128][SROW];   // 48 KB

    const int tid  = threadIdx.x;
    const int lane = tid & 31;
    const int wid  = tid >> 5;
    const int wm   = wid >> 2;          // 0..1  -> m offset wm*64
    const int wn   = wid & 3;           // 0..3  -> n offset wn*32
    const int m0   = blockIdx.y * 128;
    const int n0   = blockIdx.x * 128;

    const int ldrow = tid >> 1;         // 0..127
    const int ldhalf = (tid & 1) * 8;   // k-offset 0 or 8 (8 bf16 = 16B)

    const int g  = lane >> 2;           // group id 0..7
    const int c2 = (lane & 3) * 2;      // k-pair offset

    float acc[4][4][4];
#pragma unroll
    for (int i = 0; i < 4; i++)
#pragma unroll
        for (int j = 0; j < 4; j++)
#pragma unroll
            for (int q = 0; q < 4; q++) acc[i][j][q] = 0.0f;

    const int iters = Kd / 16;

    // prologue: stage k-tile 0 into buffer 0
    {
        cp16(&sm[0][0][ldrow][ldhalf], Ah + (size_t)(m0 + ldrow) * Kd + ldhalf);
        cp16(&sm[0][1][ldrow][ldhalf], Al + (size_t)(m0 + ldrow) * Kd + ldhalf);
        cp16(&sm[0][2][ldrow][ldhalf], Wh + (size_t)(n0 + ldrow) * Kd + ldhalf);
        cp16(&sm[0][3][ldrow][ldhalf], Wl + (size_t)(n0 + ldrow) * Kd + ldhalf);
        CP_COMMIT();
    }

    int cur = 0;
    for (int it = 0; it < iters; it++) {
        if (it + 1 < iters) {
            const int nk = (it + 1) * 16;
            const int nb = cur ^ 1;
            cp16(&sm[nb][0][ldrow][ldhalf], Ah + (size_t)(m0 + ldrow) * Kd + nk + ldhalf);
            cp16(&sm[nb][1][ldrow][ldhalf], Al + (size_t)(m0 + ldrow) * Kd + nk + ldhalf);
            cp16(&sm[nb][2][ldrow][ldhalf], Wh + (size_t)(n0 + ldrow) * Kd + nk + ldhalf);
            cp16(&sm[nb][3][ldrow][ldhalf], Wl + (size_t)(n0 + ldrow) * Kd + nk + ldhalf);
            CP_COMMIT();
            CP_WAIT(1);
        } else {
            CP_WAIT(0);
        }
        __syncthreads();

        // B fragments (hi and lo), 4 n-tiles
        unsigned bh0[4], bh1[4], bl0[4], bl1[4];
#pragma unroll
        for (int nt = 0; nt < 4; nt++) {
            const int rb = wn * 32 + nt * 8 + g;
            bh0[nt] = *(const unsigned*)&sm[cur][2][rb][c2];
            bh1[nt] = *(const unsigned*)&sm[cur][2][rb][c2 + 8];
            bl0[nt] = *(const unsigned*)&sm[cur][3][rb][c2];
            bl1[nt] = *(const unsigned*)&sm[cur][3][rb][c2 + 8];
        }

#pragma unroll
        for (int mt = 0; mt < 4; mt++) {
            const int ra = wm * 64 + mt * 16 + g;
            unsigned ah0 = *(const unsigned*)&sm[cur][0][ra][c2];
            unsigned ah1 = *(const unsigned*)&sm[cur][0][ra + 8][c2];
            unsigned ah2 = *(const unsigned*)&sm[cur][0][ra][c2 + 8];
            unsigned ah3 = *(const unsigned*)&sm[cur][0][ra + 8][c2 + 8];
            unsigned al0 = *(const unsigned*)&sm[cur][1][ra][c2];
            unsigned al1 = *(const unsigned*)&sm[cur][1][ra + 8][c2];
            unsigned al2 = *(const unsigned*)&sm[cur][1][ra][c2 + 8];
            unsigned al3 = *(const unsigned*)&sm[cur][1][ra + 8][c2 + 8];
#pragma unroll
            for (int nt = 0; nt < 4; nt++) {
                mma16816(acc[mt][nt], ah0, ah1, ah2, ah3, bh0[nt], bh1[nt]);
                mma16816(acc[mt][nt], ah0, ah1, ah2, ah3, bl0[nt], bl1[nt]);
                mma16816(acc[mt][nt], al0, al1, al2, al3, bh0[nt], bh1[nt]);
            }
        }

        __syncthreads();   // all warps done with 'cur' before it is refilled
        cur ^= 1;
    }

    // epilogue: BN + ReLU in fp32, then write fp32 or split-bf16
#pragma unroll
    for (int nt = 0; nt < 4; nt++) {
        const int col = n0 + wn * 32 + nt * 8 + c2;
        const float sc0 = scale[col],     sh0 = shift[col];
        const float sc1v = scale[col + 1], sh1v = shift[col + 1];
#pragma unroll
        for (int mt = 0; mt < 4; mt++) {
#pragma unroll
            for (int half = 0; half < 2; half++) {
                const int row = m0 + wm * 64 + mt * 16 + g + half * 8;
                const float y0 = fmaxf(fmaf(acc[mt][nt][half * 2 + 0], sc0, sh0), 0.0f);
                const float y1 = fmaxf(fmaf(acc[mt][nt][half * 2 + 1], sc1v, sh1v), 0.0f);
                if (BF16_OUT) {
                    __nv_bfloat16 h0 = __float2bfloat16(y0);
                    __nv_bfloat16 h1 = __float2bfloat16(y1);
                    __nv_bfloat16 l0 = __float2bfloat16(y0 - __bfloat162float(h0));
                    __nv_bfloat16 l1 = __float2bfloat16(y1 - __bfloat162float(h1));
                    *(__nv_bfloat162*)&outH[(size_t)row * Nd + col] = __nv_bfloat162(h0, h1);
                    *(__nv_bfloat162*)&outL[(size_t)row * Nd + col] = __nv_bfloat162(l0, l1);
                } else {
                    *(float2*)&outF[(size_t)row * Nd + col] = make_float2(y0, y1);
                }
            }
        }
    }
}

// ---------------- offsets GEMM (M x 48, K=512) fused with vote + mean partials ----------------
__global__ __launch_bounds__(256)
void offsets_kernel(const float* __restrict__ Wo, const float* __restrict__ bo,
                    const float* __restrict__ xyz)
{
    __shared__ float As[16][64];
    __shared__ float Ws[16][48];
    __shared__ float red[16][48];

    const int tid = threadIdx.x;
    const int m0 = blockIdx.x * 64;
    const int arow = tid >> 2;
    const int akb  = (tid & 3) * 4;
    const int ty = tid >> 4;
    const int tx = tid & 15;

    float acc[4][3];
#pragma unroll
    for (int i = 0; i < 4; i++)
#pragma unroll
        for (int j = 0; j < 3; j++) acc[i][j] = 0.0f;

    float4 av = *(const float4*)(g_x3 + (size_t)(m0 + arow) * C2_ + akb);
    float wv[3];
#pragma unroll
    for (int t = 0; t < 3; t++) {
        int idx = tid * 3 + t;
        int n = idx >> 4, kk = idx & 15;
        wv[t] = Wo[(size_t)n * C2_ + kk];
    }

    for (int k0 = 0; k0 < C2_; k0 += 16) {
        __syncthreads();
        As[akb + 0][arow] = av.x; As[akb + 1][arow] = av.y;
        As[akb + 2][arow] = av.z; As[akb + 3][arow] = av.w;
#pragma unroll
        for (int t = 0; t < 3; t++) {
            int idx = tid * 3 + t;
            Ws[idx & 15][idx >> 4] = wv[t];
        }
        __syncthreads();

        if (k0 + 16 < C2_) {
            av = *(const float4*)(g_x3 + (size_t)(m0 + arow) * C2_ + k0 + 16 + akb);
#pragma unroll
            for (int t = 0; t < 3; t++) {
                int idx = tid * 3 + t;
                int n = idx >> 4, kk = idx & 15;
                wv[t] = Wo[(size_t)n * C2_ + k0 + 16 + kk];
            }
        }

#pragma unroll
        for (int k = 0; k < 16; k++) {
            float a[4], b[3];
#pragma unroll
            for (int i = 0; i < 4; i++) a[i] = As[k][ty * 4 + i];
#pragma unroll
            for (int j = 0; j < 3; j++) b[j] = Ws[k][tx * 3 + j];
#pragma unroll
            for (int i = 0; i < 4; i++)
#pragma unroll
                for (int j = 0; j < 3; j++)
                    acc[i][j] = fmaf(a[i], b[j], acc[i][j]);
        }
    }

    const int b = m0 / N_;
    float psum[3] = {0.f, 0.f, 0.f};
#pragma unroll
    for (int i = 0; i < 4; i++) {
        const int m = m0 + ty * 4 + i;
#pragma unroll
        for (int j = 0; j < 3; j++) {
            const int o = tx * 3 + j;
            float v = acc[i][j] + bo[o] + xyz[(size_t)m * 3 + (o % 3)];
            g_voted[(size_t)m * O_ + o] = v;
            psum[j] += v;
        }
    }
#pragma unroll
    for (int j = 0; j < 3; j++) red[ty][tx * 3 + j] = psum[j];
    __syncthreads();
    if (tid < O_) {
        float s = 0.0f;
#pragma unroll
        for (int r = 0; r < 16; r++) s += red[r][tid];
        atomicAdd(&g_kpsum[b * O_ + tid], s);
    }
}

// ---------------- kp_pos = vote mean; also emit to output ----------------
__global__ void finalize_kp(float* __restrict__ out)
{
    int i = blockIdx.x * blockDim.x + threadIdx.x;
    if (i < B_ * O_) {
        float v = g_kpsum[i] * (1.0f / (float)N_);
        g_kpsum[i] = v;
        out[i] = v;
    }
}

// ---------------- dist -> exp(-dist) and per-(b,k) denominator ----------------
__global__ __launch_bounds__(256)
void dist_kernel()
{
    __shared__ float kp[O_];
    __shared__ float wsum[8][K_];
    const int b = blockIdx.y;
    const int tid = threadIdx.x;
    const int n = blockIdx.x * 256 + tid;
    if (tid < O_) kp[tid] = g_kpsum[b * O_ + tid];
    __syncthreads();

    const size_t m = (size_t)b * N_ + n;
    float vt[O_];
    const float4* vp = (const float4*)&g_voted[m * O_];
#pragma unroll
    for (int q = 0; q < O_ / 4; q++) ((float4*)vt)[q] = vp[q];

    float e[K_];
#pragma unroll
    for (int k = 0; k < K_; k++) {
        float dx = vt[k * 3 + 0] - kp[k * 3 + 0];
        float dy = vt[k * 3 + 1] - kp[k * 3 + 1];
        float dz = vt[k * 3 + 2] - kp[k * 3 + 2];
        float d = sqrtf(dx * dx + dy * dy + dz * dz);
        e[k] = __expf(-d);
    }
    float4* ep = (float4*)&g_ebuf[m * K_];
#pragma unroll
    for (int q = 0; q < K_ / 4; q++) ep[q] = ((float4*)e)[q];

    const int lane = tid & 31, wid = tid >> 5;
#pragma unroll
    for (int k = 0; k < K_; k++) {
        float s = e[k];
#pragma unroll
        for (int off = 16; off > 0; off >>= 1)
            s += __shfl_xor_sync(0xffffffffu, s, off);
        if (lane == 0) wsum[wid][k] = s;
    }
    __syncthreads();
    if (tid < K_) {
        float s = 0.0f;
#pragma unroll
        for (int w = 0; w < 8; w++) s += wsum[w][tid];
        atomicAdd(&g_s[b * K_ + tid], s);
    }
}

// ---------------- pooling stage 1: per-chunk partial kp_feat ----------------
__global__ __launch_bounds__(256)
void pool1_kernel(const float* __restrict__ fused)
{
    __shared__ float w_s[128][K_];
    __shared__ float sinv[K_];
    const int b = blockIdx.y, cid = blockIdx.x;
    const int tid = threadIdx.x;
    const int n0 = cid * 128;

    if (tid < K_) sinv[tid] = 1.0f / g_s[b * K_ + tid];
    __syncthreads();

#pragma unroll
    for (int t = 0; t < 2; t++) {
        int f4 = tid * 2 + t;
        int flat = f4 * 4;
        int n = flat >> 4, k0 = flat & 15;
        float4 v = *(const float4*)&g_ebuf[((size_t)b * N_ + n0 + n) * K_ + k0];
        w_s[n][k0 + 0] = v.x * sinv[k0 + 0];
        w_s[n][k0 + 1] = v.y * sinv[k0 + 1];
        w_s[n][k0 + 2] = v.z * sinv[k0 + 2];
        w_s[n][k0 + 3] = v.w * sinv[k0 + 3];
    }
    __syncthreads();

    float acc[K_];
#pragma unroll
    for (int k = 0; k < K_; k++) acc[k] = 0.0f;

    const float* fp = fused + ((size_t)b * N_ + n0) * C_ + tid;
#pragma unroll 4
    for (int n = 0; n < 128; n++) {
        float f = fp[(size_t)n * C_];
#pragma unroll
        for (int k = 0; k < K_; k++)
            acc[k] = fmaf(f, w_s[n][k], acc[k]);
    }
    float* pp = &g_partial[(((size_t)b * NCHUNK_ + cid) * K_) * C_ + tid];
#pragma unroll
    for (int k = 0; k < K_; k++) pp[(size_t)k * C_] = acc[k];
}

// ---------------- pooling stage 2: reduce chunks ----------------
__global__ void pool2_kernel()
{
    const int b = blockIdx.y, k = blockIdx.x, c = threadIdx.x;
    float s = 0.0f;
    const float* pp = &g_partial[(((size_t)b * NCHUNK_) * K_ + k) * C_ + c];
    for (int cid = 0; cid < NCHUNK_; cid++)
        s += pp[(size_t)cid * K_ * C_];
    g_kpfeat[(b * K_ + k) * C_ + c] = s;
}

// ---------------- keypoint MLP: 3 fused layers, one block per (b,k) row ----------------
__global__ __launch_bounds__(256)
void mlp_kernel(const float* __restrict__ Wm1, const float* __restrict__ Wm2,
                const float* __restrict__ Wm3, float* __restrict__ out)
{
    __shared__ float f0[C_];
    __shared__ float f1[C_];
    const int r = blockIdx.x;
    const int d = threadIdx.x;

    f0[d] = g_kpfeat[r * C_ + d];
    __syncthreads();

    {
        const float* w = Wm1 + (size_t)d * C_;
        float acc = 0.0f;
#pragma unroll 8
        for (int c = 0; c < C_; c++) acc = fmaf(f0[c], w[c], acc);
        f1[d] = fmaxf(fmaf(acc, g_scm1[d], g_shm1[d]), 0.0f);
    }
    __syncthreads();
    float v2;
    {
        const float* w = Wm2 + (size_t)d * C_;
        float acc = 0.0f;
#pragma unroll 8
        for (int c = 0; c < C_; c++) acc = fmaf(f1[c], w[c], acc);
        v2 = fmaxf(fmaf(acc, g_scm2[d], g_shm2[d]), 0.0f);
    }
    __syncthreads();
    f0[d] = v2;
    __syncthreads();
    {
        const float* w = Wm3 + (size_t)d * C_;
        float acc = 0.0f;
#pragma unroll 8
        for (int c = 0; c < C_; c++) acc = fmaf(f0[c], w[c], acc);
        out[B_ * O_ + r * C_ + d] = acc;
    }
}

extern "C" void kernel_launch(void* const* d_in, const int* in_sizes, int n_in,
                              void* d_out, int out_size)
{
    const float* fused = (const float*)d_in[0];
    const float* xyz   = (const float*)d_in[1];
    const float* W1 = (const float*)d_in[2];
    const float* g1 = (const float*)d_in[3];
    const float* b1 = (const float*)d_in[4];
    const float* m1 = (const float*)d_in[5];
    const float* v1 = (const float*)d_in[6];
    const float* W2 = (const float*)d_in[7];
    const float* g2 = (const float*)d_in[8];
    const float* b2 = (const float*)d_in[9];
    const float* m2 = (const float*)d_in[10];
    const float* v2 = (const float*)d_in[11];
    const float* W3 = (const float*)d_in[12];
    const float* g3 = (const float*)d_in[13];
    const float* b3 = (const float*)d_in[14];
    const float* m3 = (const float*)d_in[15];
    const float* v3 = (const float*)d_in[16];
    const float* Wo = (const float*)d_in[17];
    const float* bo = (const float*)d_in[18];
    const float* Wm1 = (const float*)d_in[19];
    const float* gm1 = (const float*)d_in[20];
    const float* bm1 = (const float*)d_in[21];
    const float* mm1 = (const float*)d_in[22];
    const float* vm1 = (const float*)d_in[23];
    const float* Wm2 = (const float*)d_in[24];
    const float* gm2 = (const float*)d_in[25];
    const float* bm2 = (const float*)d_in[26];
    const float* mm2 = (const float*)d_in[27];
    const float* vm2 = (const float*)d_in[28];
    const float* Wm3 = (const float*)d_in[29];
    float* out = (float*)d_out;

    prep_kernel<<<1, 512>>>(g1, b1, m1, v1, g2, b2, m2, v2, g3, b3, m3, v3,
                            gm1, bm1, mm1, vm1, gm2, bm2, mm2, vm2);

    // resolve scratch symbol addresses once (host side; not a stream op)
    static void *fh = nullptr, *fl, *x1h, *x1l, *x2h, *x2l, *x3;
    static void *w1h, *w1l, *w2h, *w2l, *w3h, *w3l;
    static void *sc1, *sh1, *sc2, *sh2, *sc3, *sh3;
    if (!fh) {
        cudaGetSymbolAddress(&fh, g_fh);   cudaGetSymbolAddress(&fl, g_fl);
        cudaGetSymbolAddress(&x1h, g_x1h); cudaGetSymbolAddress(&x1l, g_x1l);
        cudaGetSymbolAddress(&x2h, g_x2h); cudaGetSymbolAddress(&x2l, g_x2l);
        cudaGetSymbolAddress(&x3, g_x3);
        cudaGetSymbolAddress(&w1h, g_w1h); cudaGetSymbolAddress(&w1l, g_w1l);
        cudaGetSymbolAddress(&w2h, g_w2h); cudaGetSymbolAddress(&w2l, g_w2l);
        cudaGetSymbolAddress(&w3h, g_w3h); cudaGetSymbolAddress(&w3l, g_w3l);
        cudaGetSymbolAddress(&sc1, g_sc1); cudaGetSymbolAddress(&sh1, g_sh1);
        cudaGetSymbolAddress(&sc2, g_sc2); cudaGetSymbolAddress(&sh2, g_sh2);
        cudaGetSymbolAddress(&sc3, g_sc3); cudaGetSymbolAddress(&sh3, g_sh3);
    }

    // split inputs/weights into bf16 (hi, lo) planes
    {
        int n4w = C_ * C_ / 4;
        split_bf16_kernel<<<(n4w + 255) / 256, 256>>>(
            (const float4*)W1, (__nv_bfloat162*)w1h, (__nv_bfloat162*)w1l, n4w);
        split_bf16_kernel<<<(n4w + 255) / 256, 256>>>(
            (const float4*)W2, (__nv_bfloat162*)w2h, (__nv_bfloat162*)w2l, n4w);
        int n4w3 = C2_ * C_ / 4;
        split_bf16_kernel<<<(n4w3 + 255) / 256, 256>>>(
            (const float4*)W3, (__nv_bfloat162*)w3h, (__nv_bfloat162*)w3l, n4w3);
        int n4f = (int)((size_t)M_ * C_ / 4);
        split_bf16_kernel<<<(n4f + 255) / 256, 256>>>(
            (const float4*)fused, (__nv_bfloat162*)fh, (__nv_bfloat162*)fl, n4f);
    }

    // backbone GEMMs on tensor cores (split-bf16, 3 products)
    dim3 grd1(C_ / 128, M_ / 128);
    gemm_mma_bn_relu<true><<<grd1, 256>>>(
        (const __nv_bfloat16*)fh, (const __nv_bfloat16*)fl,
        (const __nv_bfloat16*)w1h, (const __nv_bfloat16*)w1l,
        nullptr, (__nv_bfloat16*)x1h, (__nv_bfloat16*)x1l,
        (const float*)sc1, (const float*)sh1, C_, C_);
    gemm_mma_bn_relu<true><<<grd1, 256>>>(
        (const __nv_bfloat16*)x1h, (const __nv_bfloat16*)x1l,
        (const __nv_bfloat16*)w2h, (const __nv_bfloat16*)w2l,
        nullptr, (__nv_bfloat16*)x2h, (__nv_bfloat16*)x2l,
        (const float*)sc2, (const float*)sh2, C_, C_);
    dim3 grd3(C2_ / 128, M_ / 128);
    gemm_mma_bn_relu<false><<<grd3, 256>>>(
        (const __nv_bfloat16*)x2h, (const __nv_bfloat16*)x2l,
        (const __nv_bfloat16*)w3h, (const __nv_bfloat16*)w3l,
        (float*)x3, nullptr, nullptr,
        (const float*)sc3, (const float*)sh3, C_, C2_);

    offsets_kernel<<<M_ / 64, 256>>>(Wo, bo, xyz);
    finalize_kp<<<(B_ * O_ + 255) / 256, 256>>>(out);

    dim3 gd(N_ / 256, B_);
    dist_kernel<<<gd, 256>>>();

    dim3 gp1(NCHUNK_, B_);
    pool1_kernel<<<gp1, 256>>>(fused);
    dim3 gp2(K_, B_);
    pool2_kernel<<<gp2, C_>>>();

    mlp_kernel<<<B_ * K_, C_>>>(Wm1, Wm2, Wm3, out);
}